// round 1
// baseline (speedup 1.0000x reference)
#include <cuda_runtime.h>

#define RPB 256   // rows per block
#define TPB 256

__global__ __launch_bounds__(TPB) void vp_lattice_kernel(
    const float* __restrict__ lt_g,
    const float* __restrict__ l0_g,
    const float* __restrict__ pl_g,
    const float* __restrict__ alpha_bars,
    const float* __restrict__ betas,
    const float* __restrict__ sigmas,
    const float* __restrict__ zn_g,
    const int*   __restrict__ traw,
    float* __restrict__ out_g,
    int B)
{
    __shared__ float s_lt[RPB * 6];
    __shared__ float s_l0[RPB * 6];
    __shared__ float s_pl[RPB * 9];
    __shared__ float s_z [RPB * 6];
    __shared__ float s_o [RPB * 6];
    __shared__ int   s_tstride;

    const int tid = threadIdx.x;
    const long long base = (long long)blockIdx.x * RPB;
    const int nrows = (int)min((long long)RPB, (long long)B - base);

    // ---- detect t dtype once per block (int64 vs int32, little-endian) ----
    if (tid == 0) {
        int acc = traw[1] | traw[3] | traw[5] | traw[7] |
                  traw[9] | traw[11] | traw[13] | traw[15];
        s_tstride = (acc == 0) ? 2 : 1;
    }

    // ---- coalesced staging loads ----
    if (nrows == RPB) {
        const float4* lt4 = (const float4*)(lt_g + base * 6);
        const float4* l04 = (const float4*)(l0_g + base * 6);
        const float4* z4  = (const float4*)(zn_g + base * 6);
        const float4* pl4 = (const float4*)(pl_g + base * 9);
        #pragma unroll
        for (int i = tid; i < RPB * 6 / 4; i += TPB) {
            ((float4*)s_lt)[i] = lt4[i];
            ((float4*)s_l0)[i] = l04[i];
            ((float4*)s_z )[i] = z4[i];
        }
        #pragma unroll
        for (int i = tid; i < RPB * 9 / 4; i += TPB)
            ((float4*)s_pl)[i] = pl4[i];
    } else {
        for (int i = tid; i < nrows * 6; i += TPB) {
            s_lt[i] = lt_g[base * 6 + i];
            s_l0[i] = l0_g[base * 6 + i];
            s_z [i] = zn_g[base * 6 + i];
        }
        for (int i = tid; i < nrows * 9; i += TPB)
            s_pl[i] = pl_g[base * 9 + i];
    }
    __syncthreads();

    if (tid < nrows) {
        const int row = tid;
        const long long g = base + row;
        const int tstride = s_tstride;
        const int tt = __ldg(&traw[g * tstride]);

        const float beta_t  = __ldg(&betas[tt]);
        const float beta_m2 = __ldg(&betas[999]);          // betas[-2], len 1001
        const float alpha   = fmaxf(1.0f - beta_t, 1.0f - beta_m2);
        const float albar   = __ldg(&alpha_bars[tt]);
        const float sigma   = __ldg(&sigmas[tt]);

        // ---- A = pred_lattice row (row-major 3x3) ----
        const float a0 = s_pl[row*9+0], a1 = s_pl[row*9+1], a2 = s_pl[row*9+2];
        const float a3 = s_pl[row*9+3], a4 = s_pl[row*9+4], a5 = s_pl[row*9+5];
        const float a6 = s_pl[row*9+6], a7 = s_pl[row*9+7], a8 = s_pl[row*9+8];

        // ---- M = A^T A (symmetric PSD) ----
        const float m00 = a0*a0 + a3*a3 + a6*a6;
        const float m11 = a1*a1 + a4*a4 + a7*a7;
        const float m22 = a2*a2 + a5*a5 + a8*a8;
        const float m01 = a0*a1 + a3*a4 + a6*a7;
        const float m02 = a0*a2 + a3*a5 + a6*a8;
        const float m12 = a1*a2 + a4*a5 + a7*a8;

        // ---- analytic eigenvalues of M (trigonometric method) ----
        const float q  = (m00 + m11 + m22) * (1.0f/3.0f);
        const float p1 = m01*m01 + m02*m02 + m12*m12;
        const float d0 = m00 - q, d1 = m11 - q, d2 = m22 - q;
        const float p2 = d0*d0 + d1*d1 + d2*d2 + 2.0f * p1;
        const float p  = sqrtf(p2 * (1.0f/6.0f));
        const float pinv = (p > 1e-12f) ? (1.0f / p) : 0.0f;

        const float b00 = d0*pinv, b11 = d1*pinv, b22 = d2*pinv;
        const float b01 = m01*pinv, b02 = m02*pinv, b12 = m12*pinv;
        float r = 0.5f * (b00*(b11*b22 - b12*b12)
                        - b01*(b01*b22 - b12*b02)
                        + b02*(b01*b12 - b11*b02));
        r = fminf(1.0f, fmaxf(-1.0f, r));
        const float phi = acosf(r) * (1.0f/3.0f);
        const float l1 = q + 2.0f * p * cosf(phi);
        const float l3 = q + 2.0f * p * cosf(phi + 2.0943951023931953f); // +2pi/3
        const float l2 = 3.0f * q - l1 - l3;

        const float s1 = sqrtf(fmaxf(l1, 0.0f));
        const float s2 = sqrtf(fmaxf(l2, 0.0f));
        const float s3 = sqrtf(fmaxf(l3, 0.0f));

        // ---- sqrt(M) via U = (aM + cI)(M + bI)^{-1} ----
        const float sa = s1 + s2 + s3;
        const float sb = s1*s2 + s1*s3 + s2*s3;
        const float sc = s1*s2*s3;

        const float n00 = m00 + sb, n11 = m11 + sb, n22 = m22 + sb;
        // adjugate of N (symmetric)
        const float c00 = n11*n22 - m12*m12;
        const float c01 = m02*m12 - m01*n22;
        const float c02 = m01*m12 - m02*n11;
        const float c11 = n00*n22 - m02*m02;
        const float c12 = m01*m02 - n00*m12;
        const float c22 = n00*n11 - m01*m01;
        float det = n00*c00 + m01*c01 + m02*c02;
        det = fmaxf(det, 1e-30f);           // N is SPD for nonzero A
        const float dinv = 1.0f / det;

        const float p00 = sa*m00 + sc, p11 = sa*m11 + sc, p22 = sa*m22 + sc;
        const float p01 = sa*m01,      p02 = sa*m02,      p12 = sa*m12;

        // U = P * C * dinv, symmetrized (matches reference (L+L^T)/2)
        const float u00 = (p00*c00 + p01*c01 + p02*c02) * dinv;
        const float u11 = (p01*c01 + p11*c11 + p12*c12) * dinv;
        const float u22 = (p02*c02 + p12*c12 + p22*c22) * dinv;
        float u01 = (p00*c01 + p01*c11 + p02*c12) * dinv;
        float u02 = (p00*c02 + p01*c12 + p02*c22) * dinv;
        float u12 = (p01*c02 + p11*c12 + p12*c22) * dinv;
        u01 = 0.5f * (u01 + (p01*c00 + p11*c01 + p12*c02) * dinv);
        u02 = 0.5f * (u02 + (p02*c00 + p12*c01 + p22*c02) * dinv);
        u12 = 0.5f * (u12 + (p02*c01 + p12*c11 + p22*c12) * dinv);

        const float vec[6] = { u00, u01, u02, u11, u12, u22 };

        const float coef  = rsqrtf(alpha + 1e-8f);
        const float scale = (1.0f - alpha) * rsqrtf(1.0f - albar + 1e-8f);
        const float zmul  = (tt > 1) ? sigma : 0.0f;

        #pragma unroll
        for (int k = 0; k < 6; k++) {
            const float ltk = s_lt[row*6 + k];
            const float pn  = ltk - 0.5f * (vec[k] + s_l0[row*6 + k]);
            s_o[row*6 + k]  = coef * (ltk - scale * pn) + zmul * s_z[row*6 + k];
        }
    }
    __syncthreads();

    // ---- coalesced staged stores ----
    if (nrows == RPB) {
        float4* o4 = (float4*)(out_g + base * 6);
        #pragma unroll
        for (int i = tid; i < RPB * 6 / 4; i += TPB)
            o4[i] = ((float4*)s_o)[i];
    } else {
        for (int i = tid; i < nrows * 6; i += TPB)
            out_g[base * 6 + i] = s_o[i];
    }
}

extern "C" void kernel_launch(void* const* d_in, const int* in_sizes, int n_in,
                              void* d_out, int out_size)
{
    const float* lt  = (const float*)d_in[0];
    const float* l0  = (const float*)d_in[1];
    const float* pl  = (const float*)d_in[2];
    const float* ab  = (const float*)d_in[3];
    const float* be  = (const float*)d_in[4];
    const float* si  = (const float*)d_in[5];
    const float* zn  = (const float*)d_in[6];
    const int*   t   = (const int*)d_in[7];
    float* out = (float*)d_out;

    const int B = in_sizes[0] / 6;          // lt is (B, 6)
    const int blocks = (B + RPB - 1) / RPB;

    vp_lattice_kernel<<<blocks, TPB>>>(lt, l0, pl, ab, be, si, zn, t, out, B);
}

// round 2
// speedup vs baseline: 1.2708x; 1.2708x over previous
#include <cuda_runtime.h>

#define RPB 256   // rows per block
#define TPB 256

__global__ __launch_bounds__(TPB, 7) void vp_lattice_kernel(
    const float* __restrict__ lt_g,
    const float* __restrict__ l0_g,
    const float* __restrict__ pl_g,
    const float* __restrict__ alpha_bars,
    const float* __restrict__ betas,
    const float* __restrict__ sigmas,
    const float* __restrict__ zn_g,
    const int*   __restrict__ traw,
    float* __restrict__ out_g,
    int B)
{
    __shared__ float s_pl   [RPB * 9];   // staged pred_lattice rows
    __shared__ float s_vec  [RPB * 6];   // per-row symmetric-factor vector
    __shared__ float s_coef [RPB];
    __shared__ float s_scale[RPB];
    __shared__ float s_zm   [RPB];
    __shared__ int   s_tstride;

    const int tid = threadIdx.x;
    const long long base = (long long)blockIdx.x * RPB;
    const int nrows = (int)min((long long)RPB, (long long)B - base);

    // ---- detect t dtype once per block (int64 vs int32, little-endian) ----
    if (tid == 0) {
        int acc = traw[1] | traw[3] | traw[5] | traw[7] |
                  traw[9] | traw[11] | traw[13] | traw[15];
        s_tstride = (acc == 0) ? 2 : 1;
    }

    // ---- stage only pred_lattice (row-gather access pattern) ----
    if (nrows == RPB) {
        const float4* pl4 = (const float4*)(pl_g + base * 9);
        #pragma unroll
        for (int i = tid; i < RPB * 9 / 4; i += TPB)
            ((float4*)s_pl)[i] = pl4[i];
    } else {
        for (int i = tid; i < nrows * 9; i += TPB)
            s_pl[i] = pl_g[base * 9 + i];
    }
    __syncthreads();

    if (tid < nrows) {
        const int row = tid;
        const long long g = base + row;
        const int tt = __ldg(&traw[g * s_tstride]);

        const float beta_t  = __ldg(&betas[tt]);
        const float beta_m2 = __ldg(&betas[999]);          // betas[-2], len 1001
        const float alpha   = fmaxf(1.0f - beta_t, 1.0f - beta_m2);
        const float albar   = __ldg(&alpha_bars[tt]);
        const float sigma   = __ldg(&sigmas[tt]);

        // ---- A = pred_lattice row (row-major 3x3) ----
        const float a0 = s_pl[row*9+0], a1 = s_pl[row*9+1], a2 = s_pl[row*9+2];
        const float a3 = s_pl[row*9+3], a4 = s_pl[row*9+4], a5 = s_pl[row*9+5];
        const float a6 = s_pl[row*9+6], a7 = s_pl[row*9+7], a8 = s_pl[row*9+8];

        // ---- M = A^T A (symmetric PSD) ----
        const float m00 = a0*a0 + a3*a3 + a6*a6;
        const float m11 = a1*a1 + a4*a4 + a7*a7;
        const float m22 = a2*a2 + a5*a5 + a8*a8;
        const float m01 = a0*a1 + a3*a4 + a6*a7;
        const float m02 = a0*a2 + a3*a5 + a6*a8;
        const float m12 = a1*a2 + a4*a5 + a7*a8;

        // ---- analytic eigenvalues of M (trigonometric method) ----
        const float q  = (m00 + m11 + m22) * (1.0f/3.0f);
        const float p1 = m01*m01 + m02*m02 + m12*m12;
        const float d0 = m00 - q, d1 = m11 - q, d2 = m22 - q;
        const float p2 = d0*d0 + d1*d1 + d2*d2 + 2.0f * p1;
        const float p  = sqrtf(p2 * (1.0f/6.0f));
        const float pinv = (p > 1e-12f) ? (1.0f / p) : 0.0f;

        const float b00 = d0*pinv, b11 = d1*pinv, b22 = d2*pinv;
        const float b01 = m01*pinv, b02 = m02*pinv, b12 = m12*pinv;
        float r = 0.5f * (b00*(b11*b22 - b12*b12)
                        - b01*(b01*b22 - b12*b02)
                        + b02*(b01*b12 - b11*b02));
        r = fminf(1.0f, fmaxf(-1.0f, r));
        const float phi = acosf(r) * (1.0f/3.0f);
        const float l1 = q + 2.0f * p * cosf(phi);
        const float l3 = q + 2.0f * p * cosf(phi + 2.0943951023931953f); // +2pi/3
        const float l2 = 3.0f * q - l1 - l3;

        const float s1 = sqrtf(fmaxf(l1, 0.0f));
        const float s2 = sqrtf(fmaxf(l2, 0.0f));
        const float s3 = sqrtf(fmaxf(l3, 0.0f));

        // ---- sqrt(M) via U = (saM + scI)(M + sbI)^{-1} ----
        const float sa = s1 + s2 + s3;
        const float sb = s1*s2 + s1*s3 + s2*s3;
        const float sc = s1*s2*s3;

        const float n00 = m00 + sb, n11 = m11 + sb, n22 = m22 + sb;
        // adjugate of N (symmetric)
        const float c00 = n11*n22 - m12*m12;
        const float c01 = m02*m12 - m01*n22;
        const float c02 = m01*m12 - m02*n11;
        const float c11 = n00*n22 - m02*m02;
        const float c12 = m01*m02 - n00*m12;
        const float c22 = n00*n11 - m01*m01;
        float det = n00*c00 + m01*c01 + m02*c02;
        det = fmaxf(det, 1e-30f);
        const float dinv = 1.0f / det;

        const float p00 = sa*m00 + sc, p11 = sa*m11 + sc, p22 = sa*m22 + sc;
        const float p01 = sa*m01,      p02 = sa*m02,      p12 = sa*m12;

        // U = P * C * dinv, symmetrized (matches reference (L+L^T)/2)
        s_vec[row*6+0] = (p00*c00 + p01*c01 + p02*c02) * dinv;
        s_vec[row*6+3] = (p01*c01 + p11*c11 + p12*c12) * dinv;
        s_vec[row*6+5] = (p02*c02 + p12*c12 + p22*c22) * dinv;
        s_vec[row*6+1] = 0.5f * ((p00*c01 + p01*c11 + p02*c12)
                               + (p01*c00 + p11*c01 + p12*c02)) * dinv;
        s_vec[row*6+2] = 0.5f * ((p00*c02 + p01*c12 + p02*c22)
                               + (p02*c00 + p12*c01 + p22*c02)) * dinv;
        s_vec[row*6+4] = 0.5f * ((p01*c02 + p11*c12 + p12*c22)
                               + (p02*c01 + p12*c11 + p22*c12)) * dinv;

        s_coef [row] = rsqrtf(alpha + 1e-8f);
        s_scale[row] = (1.0f - alpha) * rsqrtf(1.0f - albar + 1e-8f);
        s_zm   [row] = (tt > 1) ? sigma : 0.0f;
    }
    __syncthreads();

    // ---- elementwise epilogue: direct coalesced global I/O ----
    if (nrows == RPB) {
        const float4* lt4 = (const float4*)(lt_g + base * 6);
        const float4* l04 = (const float4*)(l0_g + base * 6);
        const float4* z4  = (const float4*)(zn_g + base * 6);
        float4*       o4  = (float4*)(out_g + base * 6);
        #pragma unroll
        for (int i = tid; i < RPB * 6 / 4; i += TPB) {
            const float4 a = lt4[i];
            const float4 b = l04[i];
            const float4 zz = z4[i];
            const float av[4] = { a.x, a.y, a.z, a.w };
            const float bv[4] = { b.x, b.y, b.z, b.w };
            const float zv[4] = { zz.x, zz.y, zz.z, zz.w };
            float ov[4];
            const int e0 = i * 4;
            #pragma unroll
            for (int c = 0; c < 4; c++) {
                const int e = e0 + c;
                const int row = e / 6;
                const int k   = e - row * 6;
                const float v  = s_vec[row*6 + k];
                const float pn = av[c] - 0.5f * (v + bv[c]);
                ov[c] = s_coef[row] * (av[c] - s_scale[row] * pn)
                      + s_zm[row] * zv[c];
            }
            o4[i] = make_float4(ov[0], ov[1], ov[2], ov[3]);
        }
    } else {
        for (int i = tid; i < nrows * 6; i += TPB) {
            const int row = i / 6;
            const int k   = i - row * 6;
            const float ltv = lt_g[base*6 + i];
            const float pn  = ltv - 0.5f * (s_vec[row*6+k] + l0_g[base*6 + i]);
            out_g[base*6 + i] = s_coef[row] * (ltv - s_scale[row] * pn)
                              + s_zm[row] * zn_g[base*6 + i];
        }
    }
}

extern "C" void kernel_launch(void* const* d_in, const int* in_sizes, int n_in,
                              void* d_out, int out_size)
{
    const float* lt  = (const float*)d_in[0];
    const float* l0  = (const float*)d_in[1];
    const float* pl  = (const float*)d_in[2];
    const float* ab  = (const float*)d_in[3];
    const float* be  = (const float*)d_in[4];
    const float* si  = (const float*)d_in[5];
    const float* zn  = (const float*)d_in[6];
    const int*   t   = (const int*)d_in[7];
    float* out = (float*)d_out;

    const int B = in_sizes[0] / 6;          // lt is (B, 6)
    const int blocks = (B + RPB - 1) / RPB;

    vp_lattice_kernel<<<blocks, TPB>>>(lt, l0, pl, ab, be, si, zn, t, out, B);
}

// round 3
// speedup vs baseline: 1.3586x; 1.0691x over previous
#include <cuda_runtime.h>

#define RPB 256   // rows per block
#define TPB 256

__global__ __launch_bounds__(TPB, 8) void vp_lattice_kernel(
    const float* __restrict__ lt_g,
    const float* __restrict__ l0_g,
    const float* __restrict__ pl_g,
    const float* __restrict__ alpha_bars,
    const float* __restrict__ betas,
    const float* __restrict__ sigmas,
    const float* __restrict__ zn_g,
    const int*   __restrict__ traw,
    float* __restrict__ out_g,
    int B)
{
    __shared__ float s_pl   [RPB * 9];   // staged pred_lattice rows
    __shared__ float s_vec  [RPB * 6];   // per-row symmetric-factor vector
    __shared__ float s_coef [RPB];
    __shared__ float s_scale[RPB];
    __shared__ float s_zm   [RPB];
    __shared__ int   s_tstride;

    const int tid = threadIdx.x;
    const long long base = (long long)blockIdx.x * RPB;
    const int nrows = (int)min((long long)RPB, (long long)B - base);

    // ---- detect t dtype once per block (int64 vs int32, little-endian) ----
    if (tid == 0) {
        int acc = traw[1] | traw[3] | traw[5] | traw[7] |
                  traw[9] | traw[11] | traw[13] | traw[15];
        s_tstride = (acc == 0) ? 2 : 1;
    }

    // ---- stage only pred_lattice (row-gather access pattern) ----
    if (nrows == RPB) {
        const float4* pl4 = (const float4*)(pl_g + base * 9);
        #pragma unroll
        for (int i = tid; i < RPB * 9 / 4; i += TPB)
            ((float4*)s_pl)[i] = __ldcs(&pl4[i]);
    } else {
        for (int i = tid; i < nrows * 9; i += TPB)
            s_pl[i] = pl_g[base * 9 + i];
    }
    __syncthreads();

    if (tid < nrows) {
        const int row = tid;
        const long long g = base + row;
        const int tt = __ldg(&traw[g * s_tstride]);

        const float beta_t  = __ldg(&betas[tt]);
        const float beta_m2 = __ldg(&betas[999]);          // betas[-2], len 1001
        const float alpha   = fmaxf(1.0f - beta_t, 1.0f - beta_m2);
        const float albar   = __ldg(&alpha_bars[tt]);
        const float sigma   = __ldg(&sigmas[tt]);

        // ---- A = pred_lattice row (row-major 3x3) ----
        const float a0 = s_pl[row*9+0], a1 = s_pl[row*9+1], a2 = s_pl[row*9+2];
        const float a3 = s_pl[row*9+3], a4 = s_pl[row*9+4], a5 = s_pl[row*9+5];
        const float a6 = s_pl[row*9+6], a7 = s_pl[row*9+7], a8 = s_pl[row*9+8];

        // ---- M = A^T A (symmetric PSD) ----
        const float m00 = a0*a0 + a3*a3 + a6*a6;
        const float m11 = a1*a1 + a4*a4 + a7*a7;
        const float m22 = a2*a2 + a5*a5 + a8*a8;
        const float m01 = a0*a1 + a3*a4 + a6*a7;
        const float m02 = a0*a2 + a3*a5 + a6*a8;
        const float m12 = a1*a2 + a4*a5 + a7*a8;

        // ---- invariants of M:  e1=tr, e2=sum 2x2 minors, e3=det ----
        const float e1 = m00 + m11 + m22;
        const float e2 = (m00*m11 - m01*m01)
                       + (m00*m22 - m02*m02)
                       + (m11*m22 - m12*m12);
        const float e3 = m00*(m11*m22 - m12*m12)
                       - m01*(m01*m22 - m12*m02)
                       + m02*(m01*m12 - m11*m02);

        // ---- elementary symmetric functions of singular values s_i = sqrt(lambda_i)
        //      sc = s1 s2 s3 = sqrt(e3)
        //      sa = sum s_i,  sb = sum s_i s_j  solve:
        //      sa^2 = e1 + 2 sb ;  sb^2 = e2 + 2 sc sa
        //      fixed point, loop gain sc/(sa*sb) <= 1/9  (AM-GM)
        const float sc = sqrtf(fmaxf(e3, 0.0f));
        const float e2c = fmaxf(e2, 0.0f);
        float sb = sqrtf(e2c);
        float sa = sqrtf(fmaxf(e1 + 2.0f * sb, 0.0f));
        #pragma unroll
        for (int it = 0; it < 7; it++) {
            sb = sqrtf(fmaxf(e2c + 2.0f * sc * sa, 0.0f));
            sa = sqrtf(fmaxf(e1 + 2.0f * sb, 0.0f));
        }

        // ---- U = sqrt(M) = sa*I + k*adj(N),  N = M + sb*I,
        //      k = (sc - sa*sb) / det(N)   (exactly symmetric)
        const float n00 = m00 + sb, n11 = m11 + sb, n22 = m22 + sb;
        const float c00 = n11*n22 - m12*m12;
        const float c01 = m02*m12 - m01*n22;
        const float c02 = m01*m12 - n11*m02;
        const float c11 = n00*n22 - m02*m02;
        const float c12 = m01*m02 - n00*m12;
        const float c22 = n00*n11 - m01*m01;
        const float det = fmaxf(n00*c00 + m01*c01 + m02*c02, 1e-30f);
        const float k   = (sc - sa * sb) / det;

        s_vec[row*6+0] = sa + k * c00;
        s_vec[row*6+1] =      k * c01;
        s_vec[row*6+2] =      k * c02;
        s_vec[row*6+3] = sa + k * c11;
        s_vec[row*6+4] =      k * c12;
        s_vec[row*6+5] = sa + k * c22;

        s_coef [row] = rsqrtf(alpha + 1e-8f);
        s_scale[row] = (1.0f - alpha) * rsqrtf(1.0f - albar + 1e-8f);
        s_zm   [row] = (tt > 1) ? sigma : 0.0f;
    }
    __syncthreads();

    // ---- elementwise epilogue: direct coalesced global I/O ----
    if (nrows == RPB) {
        const float4* lt4 = (const float4*)(lt_g + base * 6);
        const float4* l04 = (const float4*)(l0_g + base * 6);
        const float4* z4  = (const float4*)(zn_g + base * 6);
        float4*       o4  = (float4*)(out_g + base * 6);
        #pragma unroll
        for (int i = tid; i < RPB * 6 / 4; i += TPB) {
            const float4 a  = __ldcs(&lt4[i]);
            const float4 b  = __ldcs(&l04[i]);
            const float4 zz = __ldcs(&z4[i]);
            const float av[4] = { a.x, a.y, a.z, a.w };
            const float bv[4] = { b.x, b.y, b.z, b.w };
            const float zv[4] = { zz.x, zz.y, zz.z, zz.w };
            float ov[4];
            const int e0 = i * 4;
            #pragma unroll
            for (int c = 0; c < 4; c++) {
                const int e = e0 + c;
                const int row = e / 6;
                const int kk  = e - row * 6;
                const float v  = s_vec[row*6 + kk];
                const float pn = av[c] - 0.5f * (v + bv[c]);
                ov[c] = s_coef[row] * (av[c] - s_scale[row] * pn)
                      + s_zm[row] * zv[c];
            }
            __stcs(&o4[i], make_float4(ov[0], ov[1], ov[2], ov[3]));
        }
    } else {
        for (int i = tid; i < nrows * 6; i += TPB) {
            const int row = i / 6;
            const int kk  = i - row * 6;
            const float ltv = lt_g[base*6 + i];
            const float pn  = ltv - 0.5f * (s_vec[row*6+kk] + l0_g[base*6 + i]);
            out_g[base*6 + i] = s_coef[row] * (ltv - s_scale[row] * pn)
                              + s_zm[row] * zn_g[base*6 + i];
        }
    }
}

extern "C" void kernel_launch(void* const* d_in, const int* in_sizes, int n_in,
                              void* d_out, int out_size)
{
    const float* lt  = (const float*)d_in[0];
    const float* l0  = (const float*)d_in[1];
    const float* pl  = (const float*)d_in[2];
    const float* ab  = (const float*)d_in[3];
    const float* be  = (const float*)d_in[4];
    const float* si  = (const float*)d_in[5];
    const float* zn  = (const float*)d_in[6];
    const int*   t   = (const int*)d_in[7];
    float* out = (float*)d_out;

    const int B = in_sizes[0] / 6;          // lt is (B, 6)
    const int blocks = (B + RPB - 1) / RPB;

    vp_lattice_kernel<<<blocks, TPB>>>(lt, l0, pl, ab, be, si, zn, t, out, B);
}

// round 4
// speedup vs baseline: 1.4491x; 1.0667x over previous
#include <cuda_runtime.h>

#define RPB 256   // rows per block
#define TPB 256

__device__ __forceinline__ float fsqrt_ap(float x) {
    float r; asm("sqrt.approx.f32 %0, %1;" : "=f"(r) : "f"(x)); return r;
}
__device__ __forceinline__ float frsqrt_ap(float x) {
    float r; asm("rsqrt.approx.f32 %0, %1;" : "=f"(r) : "f"(x)); return r;
}
__device__ __forceinline__ float frcp_ap(float x) {
    float r; asm("rcp.approx.f32 %0, %1;" : "=f"(r) : "f"(x)); return r;
}

__global__ __launch_bounds__(TPB, 8) void vp_lattice_kernel(
    const float* __restrict__ lt_g,
    const float* __restrict__ l0_g,
    const float* __restrict__ pl_g,
    const float* __restrict__ alpha_bars,
    const float* __restrict__ betas,
    const float* __restrict__ sigmas,
    const float* __restrict__ zn_g,
    const int*   __restrict__ traw,
    float* __restrict__ out_g,
    int B)
{
    __shared__ float s_pl   [RPB * 9];   // staged pred_lattice rows
    __shared__ float s_vec  [RPB * 6];   // per-row symmetric-factor vector
    __shared__ float s_coef [RPB];
    __shared__ float s_scale[RPB];
    __shared__ float s_zm   [RPB];
    __shared__ int   s_tstride;

    const int tid = threadIdx.x;
    const long long base = (long long)blockIdx.x * RPB;
    const int nrows = (int)min((long long)RPB, (long long)B - base);

    // ---- detect t dtype once per block (int64 vs int32, little-endian) ----
    if (tid == 0) {
        int acc = traw[1] | traw[3] | traw[5] | traw[7] |
                  traw[9] | traw[11] | traw[13] | traw[15];
        s_tstride = (acc == 0) ? 2 : 1;
    }

    // ---- stage only pred_lattice (row-gather access pattern) ----
    if (nrows == RPB) {
        const float4* pl4 = (const float4*)(pl_g + base * 9);
        #pragma unroll
        for (int i = tid; i < RPB * 9 / 4; i += TPB)
            ((float4*)s_pl)[i] = __ldcs(&pl4[i]);
    } else {
        for (int i = tid; i < nrows * 9; i += TPB)
            s_pl[i] = pl_g[base * 9 + i];
    }
    __syncthreads();

    if (tid < nrows) {
        const int row = tid;
        const long long g = base + row;
        const int tt = __ldg(&traw[g * s_tstride]);

        const float beta_t  = __ldg(&betas[tt]);
        const float beta_m2 = __ldg(&betas[999]);          // betas[-2], len 1001
        const float alpha   = fmaxf(1.0f - beta_t, 1.0f - beta_m2);
        const float albar   = __ldg(&alpha_bars[tt]);
        const float sigma   = __ldg(&sigmas[tt]);

        // ---- A = pred_lattice row (row-major 3x3) ----
        const float a0 = s_pl[row*9+0], a1 = s_pl[row*9+1], a2 = s_pl[row*9+2];
        const float a3 = s_pl[row*9+3], a4 = s_pl[row*9+4], a5 = s_pl[row*9+5];
        const float a6 = s_pl[row*9+6], a7 = s_pl[row*9+7], a8 = s_pl[row*9+8];

        // ---- M = A^T A (symmetric PSD) ----
        const float m00 = a0*a0 + a3*a3 + a6*a6;
        const float m11 = a1*a1 + a4*a4 + a7*a7;
        const float m22 = a2*a2 + a5*a5 + a8*a8;
        const float m01 = a0*a1 + a3*a4 + a6*a7;
        const float m02 = a0*a2 + a3*a5 + a6*a8;
        const float m12 = a1*a2 + a4*a5 + a7*a8;

        // ---- invariants of M:  e1=tr, e2=sum 2x2 minors, e3=det ----
        const float e1 = m00 + m11 + m22;
        const float e2 = (m00*m11 - m01*m01)
                       + (m00*m22 - m02*m02)
                       + (m11*m22 - m12*m12);
        const float e3 = m00*(m11*m22 - m12*m12)
                       - m01*(m01*m22 - m12*m02)
                       + m02*(m01*m12 - m11*m02);

        // ---- elementary symmetric functions of singular values s_i = sqrt(lambda_i)
        //      sc = sqrt(e3);  sa^2 = e1 + 2 sb ;  sb^2 = e2 + 2 sc sa
        //      fixed point, loop gain sc/(sa*sb) <= 1/9 (AM-GM); 5 iters -> <1e-5
        const float sc  = fsqrt_ap(fmaxf(e3, 0.0f));
        const float e2c = fmaxf(e2, 0.0f);
        float sb = fsqrt_ap(e2c);
        float sa = fsqrt_ap(fmaxf(e1 + 2.0f * sb, 0.0f));
        #pragma unroll
        for (int it = 0; it < 5; it++) {
            sb = fsqrt_ap(fmaxf(e2c + 2.0f * sc * sa, 0.0f));
            sa = fsqrt_ap(fmaxf(e1 + 2.0f * sb, 0.0f));
        }

        // ---- U = sqrt(M) = sa*I + k*adj(N),  N = M + sb*I,
        //      k = (sc - sa*sb) / det(N)   (exactly symmetric)
        const float n00 = m00 + sb, n11 = m11 + sb, n22 = m22 + sb;
        const float c00 = n11*n22 - m12*m12;
        const float c01 = m02*m12 - m01*n22;
        const float c02 = m01*m12 - n11*m02;
        const float c11 = n00*n22 - m02*m02;
        const float c12 = m01*m02 - n00*m12;
        const float c22 = n00*n11 - m01*m01;
        const float det = fmaxf(n00*c00 + m01*c01 + m02*c02, 1e-30f);
        const float k   = (sc - sa * sb) * frcp_ap(det);

        s_vec[row*6+0] = sa + k * c00;
        s_vec[row*6+1] =      k * c01;
        s_vec[row*6+2] =      k * c02;
        s_vec[row*6+3] = sa + k * c11;
        s_vec[row*6+4] =      k * c12;
        s_vec[row*6+5] = sa + k * c22;

        s_coef [row] = frsqrt_ap(alpha + 1e-8f);
        s_scale[row] = (1.0f - alpha) * frsqrt_ap(1.0f - albar + 1e-8f);
        s_zm   [row] = (tt > 1) ? sigma : 0.0f;
    }
    __syncthreads();

    // ---- elementwise epilogue: direct coalesced global I/O ----
    if (nrows == RPB) {
        const float4* lt4 = (const float4*)(lt_g + base * 6);
        const float4* l04 = (const float4*)(l0_g + base * 6);
        const float4* z4  = (const float4*)(zn_g + base * 6);
        float4*       o4  = (float4*)(out_g + base * 6);
        #pragma unroll
        for (int i = tid; i < RPB * 6 / 4; i += TPB) {
            const float4 a  = __ldcs(&lt4[i]);
            const float4 b  = __ldcs(&l04[i]);
            const float4 zz = __ldcs(&z4[i]);
            const float av[4] = { a.x, a.y, a.z, a.w };
            const float bv[4] = { b.x, b.y, b.z, b.w };
            const float zv[4] = { zz.x, zz.y, zz.z, zz.w };
            float ov[4];
            const int e0 = i * 4;
            #pragma unroll
            for (int c = 0; c < 4; c++) {
                const int e = e0 + c;
                const int row = e / 6;
                const int kk  = e - row * 6;
                const float v  = s_vec[row*6 + kk];
                const float pn = av[c] - 0.5f * (v + bv[c]);
                ov[c] = s_coef[row] * (av[c] - s_scale[row] * pn)
                      + s_zm[row] * zv[c];
            }
            __stcs(&o4[i], make_float4(ov[0], ov[1], ov[2], ov[3]));
        }
    } else {
        for (int i = tid; i < nrows * 6; i += TPB) {
            const int row = i / 6;
            const int kk  = i - row * 6;
            const float ltv = lt_g[base*6 + i];
            const float pn  = ltv - 0.5f * (s_vec[row*6+kk] + l0_g[base*6 + i]);
            out_g[base*6 + i] = s_coef[row] * (ltv - s_scale[row] * pn)
                              + s_zm[row] * zn_g[base*6 + i];
        }
    }
}

extern "C" void kernel_launch(void* const* d_in, const int* in_sizes, int n_in,
                              void* d_out, int out_size)
{
    const float* lt  = (const float*)d_in[0];
    const float* l0  = (const float*)d_in[1];
    const float* pl  = (const float*)d_in[2];
    const float* ab  = (const float*)d_in[3];
    const float* be  = (const float*)d_in[4];
    const float* si  = (const float*)d_in[5];
    const float* zn  = (const float*)d_in[6];
    const int*   t   = (const int*)d_in[7];
    float* out = (float*)d_out;

    const int B = in_sizes[0] / 6;          // lt is (B, 6)
    const int blocks = (B + RPB - 1) / RPB;

    vp_lattice_kernel<<<blocks, TPB>>>(lt, l0, pl, ab, be, si, zn, t, out, B);
}